// round 7
// baseline (speedup 1.0000x reference)
#include <cuda_runtime.h>
#include <cuda_bf16.h>
#include <cuda_fp16.h>

// Problem: out[i] = mean_{p != i} ( tanh( [x_i, x_p] @ W1 + b1 ) @ W2 + b2 )
// Restructured: A = x@W1[:64] + b1, B = x@W1[64:]
//   out[i] = ( (sum_p tanh(A[i]+B[p]) - tanh(A[i]+B[i])) / 1023 ) @ W2 + b2

#define N_E    1024
#define N_IN   64
#define HIDDEN 128
#define OUTD   64
#define PSPLIT 8
#define PCHUNK (N_E / PSPLIT)   // 128
#define TI     8                // i-rows per block in phase 2
#define TIG    4                // i-rows per i-group (2 groups per block)
#define TI1    2                // i-rows per block in phase 1
#define FSPLIT 4                // f-dim split in phase 1
#define FPT    (N_IN / FSPLIT)  // 16
#define TI3    8                // i-rows per block in phase 3

// Scratch (device globals — no runtime allocation allowed)
__device__ float g_A[N_E * HIDDEN];                   // 512 KB
__device__ float g_B[N_E * HIDDEN];                   // 512 KB
__device__ float g_Sp[PSPLIT * N_E * HIDDEN];         // 4 MB partial sums

__device__ __forceinline__ float tanh_fast(float x) {
    float y;
    asm("tanh.approx.f32 %0, %1;" : "=f"(y) : "f"(x));
    return y;
}

// ---------------------------------------------------------------------------
// Phase 1: A[i,h] = b1[h] + sum_f x[i,f]*W1[f,h];  B[i,h] = sum_f x[i,f]*W1[64+f,h]
// 512 blocks x 512 threads. f-dim split 4 ways (chain depth 16, not 64),
// shared-memory reduce across f-groups. ~55 warps/SM.
// ---------------------------------------------------------------------------
__global__ void __launch_bounds__(FSPLIT * HIDDEN) phase1_kernel(
    const float* __restrict__ x, const float* __restrict__ W1,
    const float* __restrict__ b1)
{
    const int t  = threadIdx.x;
    const int h  = t & (HIDDEN - 1);
    const int fg = t >> 7;               // f-group 0..3
    const int i0 = blockIdx.x * TI1;

    __shared__ float xs[TI1][N_IN];
    __shared__ float red[FSPLIT][2][TI1][HIDDEN];   // 8 KB

    if (t < TI1 * N_IN) xs[t >> 6][t & 63] = x[i0 * N_IN + t];
    __syncthreads();

    float a[TI1], b[TI1];
    #pragma unroll
    for (int k = 0; k < TI1; k++) { a[k] = 0.0f; b[k] = 0.0f; }

    const int fbase = fg * FPT;
    #pragma unroll
    for (int ff = 0; ff < FPT; ff++) {
        const int f = fbase + ff;
        const float wa = W1[f * HIDDEN + h];
        const float wb = W1[(N_IN + f) * HIDDEN + h];
        #pragma unroll
        for (int k = 0; k < TI1; k++) {
            const float xv = xs[k][f];
            a[k] = fmaf(xv, wa, a[k]);
            b[k] = fmaf(xv, wb, b[k]);
        }
    }

    #pragma unroll
    for (int k = 0; k < TI1; k++) {
        red[fg][0][k][h] = a[k];
        red[fg][1][k][h] = b[k];
    }
    __syncthreads();

    if (fg == 0) {
        const float bb = b1[h];
        #pragma unroll
        for (int k = 0; k < TI1; k++) {
            float av = a[k] + red[1][0][k][h] + red[2][0][k][h] + red[3][0][k][h];
            float bv = b[k] + red[1][1][k][h] + red[2][1][k][h] + red[3][1][k][h];
            g_A[(i0 + k) * HIDDEN + h] = av + bb;
            g_B[(i0 + k) * HIDDEN + h] = bv;
        }
    }
}

// ---------------------------------------------------------------------------
// Phase 2 (dominant): partial sums of tanh(A[i]+B[p]) using tanh.approx.f16x2
// (2 tanh per MUFU op). Args computed in f32, packed per-pair; half2
// accumulation limited to 4 partners before f32 flush (precision).
// Grid (128 i-tiles, 8 p-chunks) = 1024 CTAs x 128 threads.
// Thread = (h-pair 0..63) x (i-group 0..1), 4 i-rows per group.
// ---------------------------------------------------------------------------
__global__ void __launch_bounds__(128) phase2_kernel()
{
    const int t  = threadIdx.x;
    const int hp = t & 63;               // h-pair: handles h=2hp, 2hp+1
    const int ig = t >> 6;               // i-group
    const int i0 = blockIdx.x * TI + ig * TIG;
    const int p0 = blockIdx.y * PCHUNK;

    float a0[TIG], a1[TIG], sx[TIG], sy[TIG];
    #pragma unroll
    for (int k = 0; k < TIG; k++) {
        const float2 av = *(const float2*)&g_A[(i0 + k) * HIDDEN + 2 * hp];
        a0[k] = av.x; a1[k] = av.y;
        sx[k] = 0.0f; sy[k] = 0.0f;
    }

    const float2* __restrict__ Bp =
        (const float2*)&g_B[p0 * HIDDEN + 2 * hp];

    for (int pb = 0; pb < PCHUNK; pb += 4) {
        __half2 hacc[TIG];
        #pragma unroll
        for (int k = 0; k < TIG; k++) hacc[k] = __float2half2_rn(0.0f);

        #pragma unroll
        for (int pp = 0; pp < 4; pp++) {
            const float2 bv = Bp[(pb + pp) * (HIDDEN / 2)];
            #pragma unroll
            for (int k = 0; k < TIG; k++) {
                __half2 arg = __floats2half2_rn(a0[k] + bv.x, a1[k] + bv.y);
                unsigned int u = *reinterpret_cast<unsigned int*>(&arg);
                unsigned int r;
                asm("tanh.approx.f16x2 %0, %1;" : "=r"(r) : "r"(u));
                hacc[k] = __hadd2(hacc[k], *reinterpret_cast<__half2*>(&r));
            }
        }

        #pragma unroll
        for (int k = 0; k < TIG; k++) {
            const float2 f = __half22float2(hacc[k]);
            sx[k] += f.x; sy[k] += f.y;
        }
    }

    #pragma unroll
    for (int k = 0; k < TIG; k++) {
        *(float2*)&g_Sp[(blockIdx.y * N_E + i0 + k) * HIDDEN + 2 * hp] =
            make_float2(sx[k], sy[k]);
    }
}

// ---------------------------------------------------------------------------
// Phase 3: reduce partials, remove self term, scale, project through W2, add b2.
// 8 entities per block -> W2 read once per 8 i. Shared s transposed [h][ii]
// so the GEMV inner loop uses two float4 LDS per hidden index.
// ---------------------------------------------------------------------------
__global__ void __launch_bounds__(128) phase3_kernel(
    const float* __restrict__ W2, const float* __restrict__ b2,
    float* __restrict__ out)
{
    const int i0 = blockIdx.x * TI3;
    const int t  = threadIdx.x;

    __shared__ __align__(16) float s2[HIDDEN][TI3];   // 4 KB
    __shared__ float po[2][TI3][OUTD];                // 4 KB

    #pragma unroll
    for (int ii = 0; ii < TI3; ii++) {
        const int i = i0 + ii;
        float v = 0.0f;
        #pragma unroll
        for (int c = 0; c < PSPLIT; c++)
            v += g_Sp[(c * N_E + i) * HIDDEN + t];
        // self term: partner list excludes p == i (f32 tanh: exactness of the
        // correction term matters more than its speed — it's 1 op)
        const float self_t = tanh_fast(g_A[i * HIDDEN + t] + g_B[i * HIDDEN + t]);
        s2[t][ii] = (v - self_t) * (1.0f / (float)(N_E - 1));
    }
    __syncthreads();

    const int o    = t & (OUTD - 1);
    const int half = t >> 6;
    float acc[TI3];
    #pragma unroll
    for (int ii = 0; ii < TI3; ii++) acc[ii] = 0.0f;

    #pragma unroll 8
    for (int hh = 0; hh < HIDDEN / 2; hh++) {
        const int hid = half * (HIDDEN / 2) + hh;
        const float w = W2[hid * OUTD + o];
        const float4 sa = *(const float4*)&s2[hid][0];
        const float4 sb = *(const float4*)&s2[hid][4];
        acc[0] = fmaf(sa.x, w, acc[0]);
        acc[1] = fmaf(sa.y, w, acc[1]);
        acc[2] = fmaf(sa.z, w, acc[2]);
        acc[3] = fmaf(sa.w, w, acc[3]);
        acc[4] = fmaf(sb.x, w, acc[4]);
        acc[5] = fmaf(sb.y, w, acc[5]);
        acc[6] = fmaf(sb.z, w, acc[6]);
        acc[7] = fmaf(sb.w, w, acc[7]);
    }

    #pragma unroll
    for (int ii = 0; ii < TI3; ii++) po[half][ii][o] = acc[ii];
    __syncthreads();

    if (t < OUTD) {
        const float bb = b2[t];
        #pragma unroll
        for (int ii = 0; ii < TI3; ii++)
            out[(i0 + ii) * OUTD + t] = po[0][ii][t] + po[1][ii][t] + bb;
    }
}

// ---------------------------------------------------------------------------
extern "C" void kernel_launch(void* const* d_in, const int* in_sizes, int n_in,
                              void* d_out, int out_size)
{
    // Map inputs by element count (all distinct): x=65536, W1=16384, b1=128,
    // W2=8192, b2=64.
    const float *x = nullptr, *W1 = nullptr, *b1 = nullptr, *W2 = nullptr, *b2 = nullptr;
    for (int i = 0; i < n_in; i++) {
        switch (in_sizes[i]) {
            case N_E * N_IN:          x  = (const float*)d_in[i]; break; // 65536
            case 2 * N_IN * HIDDEN:   W1 = (const float*)d_in[i]; break; // 16384
            case HIDDEN:              b1 = (const float*)d_in[i]; break; // 128
            case HIDDEN * OUTD:       W2 = (const float*)d_in[i]; break; // 8192
            case OUTD:                b2 = (const float*)d_in[i]; break; // 64
            default: break;
        }
    }
    float* out = (float*)d_out;

    phase1_kernel<<<N_E / TI1, FSPLIT * HIDDEN>>>(x, W1, b1);

    dim3 g2(N_E / TI, PSPLIT);
    phase2_kernel<<<g2, 128>>>();

    phase3_kernel<<<N_E / TI3, 128>>>(W2, b2, out);
}